// round 3
// baseline (speedup 1.0000x reference)
#include <cuda_runtime.h>
#include <cuda_bf16.h>
#include <math.h>
#include <stdint.h>

// Instant-NGP HashGrid encoding
//   x:     [N, 3]  float32, coords in [0,1)
//   table: [16, 2^19, 2] float32
//   out:   [N, 32] float32  (out[p, l*2 + f])
//
// One thread per (point, level). Key trick: the spatial hash uses prime 1 for
// the x dimension, so h(x+1) = h(x) ^ 1 when x is even -> the two x-corners of
// each (y,z) pair live in the SAME aligned 16B chunk of the table. Each (y,z)
// corner pair is fetched with one LDG.128 (plus a half-warp-predicated second
// LDG.128 for odd x), cutting L1tex wavefronts ~25% vs 8x LDG.64.

#define NGP_LEVELS 16
#define NGP_LOG2T  19
#define NGP_T      (1u << NGP_LOG2T)
#define NGP_TMASK  (NGP_T - 1u)

#define PRIME_Y 2654435761u
#define PRIME_Z 805459861u

struct ResArr { float r[NGP_LEVELS]; };

__device__ __forceinline__ void store_cs_f2(float2* p, float a, float b) {
    asm volatile("st.global.cs.v2.f32 [%0], {%1, %2};"
                 :: "l"(p), "f"(a), "f"(b) : "memory");
}

__device__ __forceinline__ float2 sel_half(float4 v, uint32_t bit) {
    // bit==0 -> (x,y) = entry (chunk*2), bit==1 -> (z,w) = entry (chunk*2+1)
    return bit ? make_float2(v.z, v.w) : make_float2(v.x, v.y);
}

__global__ __launch_bounds__(256)
void ngp_hashgrid_kernel(const float* __restrict__ x,
                         const float* __restrict__ table,
                         float2* __restrict__ out,
                         ResArr res,
                         int n_points)
{
    int tid = blockIdx.x * blockDim.x + threadIdx.x;
    int point = tid >> 4;
    int level = tid & 15;
    if (point >= n_points) return;

    const float cx = __ldg(x + point * 3 + 0);
    const float cy = __ldg(x + point * 3 + 1);
    const float cz = __ldg(x + point * 3 + 2);

    const float r = res.r[level];

    const float px = cx * r;
    const float py = cy * r;
    const float pz = cz * r;

    const float p0x = floorf(px);
    const float p0y = floorf(py);
    const float p0z = floorf(pz);

    const float fx = px - p0x;
    const float fy = py - p0y;
    const float fz = pz - p0z;

    const uint32_t ix = (uint32_t)p0x;
    const uint32_t iy = (uint32_t)p0y;
    const uint32_t iz = (uint32_t)p0z;

    // factored spatial hash: h = (x*1) ^ (y*PRIME_Y) ^ (z*PRIME_Z)
    const uint32_t hx0 = ix;
    const uint32_t hx1 = ix + 1u;
    const uint32_t hy0 = iy * PRIME_Y;
    const uint32_t hy1 = (iy + 1u) * PRIME_Y;
    const uint32_t hz0 = iz * PRIME_Z;
    const uint32_t hz1 = (iz + 1u) * PRIME_Z;

    const uint32_t m00 = hy0 ^ hz0;   // (y0, z0)
    const uint32_t m10 = hy1 ^ hz0;   // (y1, z0)
    const uint32_t m01 = hy0 ^ hz1;   // (y0, z1)
    const uint32_t m11 = hy1 ^ hz1;   // (y1, z1)

    // table indices for x0 and x1 at each (y,z) corner
    const uint32_t h000 = (hx0 ^ m00) & NGP_TMASK;
    const uint32_t h010 = (hx0 ^ m10) & NGP_TMASK;
    const uint32_t h001 = (hx0 ^ m01) & NGP_TMASK;
    const uint32_t h011 = (hx0 ^ m11) & NGP_TMASK;
    const uint32_t h100 = (hx1 ^ m00) & NGP_TMASK;
    const uint32_t h110 = (hx1 ^ m10) & NGP_TMASK;
    const uint32_t h101 = (hx1 ^ m01) & NGP_TMASK;
    const uint32_t h111 = (hx1 ^ m11) & NGP_TMASK;

    const float4* __restrict__ tl4 =
        reinterpret_cast<const float4*>(table) + (uint32_t)level * (NGP_T / 2);

    // Unconditional: chunk holding the x0 corner. When ix is even this chunk
    // ALSO holds the x1 corner (h1 = h0 ^ 1).
    float4 a00 = __ldg(tl4 + (h000 >> 1));
    float4 a10 = __ldg(tl4 + (h010 >> 1));
    float4 a01 = __ldg(tl4 + (h001 >> 1));
    float4 a11 = __ldg(tl4 + (h011 >> 1));

    // Predicated (only odd-x lanes, ~half the warp): chunk holding x1 corner.
    float4 b00 = a00, b10 = a10, b01 = a01, b11 = a11;
    if (ix & 1u) {
        b00 = __ldg(tl4 + (h100 >> 1));
        b10 = __ldg(tl4 + (h110 >> 1));
        b01 = __ldg(tl4 + (h101 >> 1));
        b11 = __ldg(tl4 + (h111 >> 1));
    }
    // Selection: x0 corner = half (h0xx & 1) of a; x1 corner = half (h1xx & 1)
    // of b. (When ix is even, b == a and h1 = h0^1, so this picks the other
    // half of the same chunk — exactly the paired entry.)
    const float2 f000 = sel_half(a00, h000 & 1u);
    const float2 f010 = sel_half(a10, h010 & 1u);
    const float2 f001 = sel_half(a01, h001 & 1u);
    const float2 f011 = sel_half(a11, h011 & 1u);
    const float2 f100 = sel_half(b00, h100 & 1u);
    const float2 f110 = sel_half(b10, h110 & 1u);
    const float2 f101 = sel_half(b01, h101 & 1u);
    const float2 f111 = sel_half(b11, h111 & 1u);

    const float gx = 1.0f - fx;
    const float gy = 1.0f - fy;
    const float gz = 1.0f - fz;

    const float wz0y0 = gy * gz;
    const float wz0y1 = fy * gz;
    const float wz1y0 = gy * fz;
    const float wz1y1 = fy * fz;

    const float w000 = gx * wz0y0;
    const float w100 = fx * wz0y0;
    const float w010 = gx * wz0y1;
    const float w110 = fx * wz0y1;
    const float w001 = gx * wz1y0;
    const float w101 = fx * wz1y0;
    const float w011 = gx * wz1y1;
    const float w111 = fx * wz1y1;

    float o0 = w000 * f000.x;
    float o1 = w000 * f000.y;
    o0 = fmaf(w100, f100.x, o0);  o1 = fmaf(w100, f100.y, o1);
    o0 = fmaf(w010, f010.x, o0);  o1 = fmaf(w010, f010.y, o1);
    o0 = fmaf(w110, f110.x, o0);  o1 = fmaf(w110, f110.y, o1);
    o0 = fmaf(w001, f001.x, o0);  o1 = fmaf(w001, f001.y, o1);
    o0 = fmaf(w101, f101.x, o0);  o1 = fmaf(w101, f101.y, o1);
    o0 = fmaf(w011, f011.x, o0);  o1 = fmaf(w011, f011.y, o1);
    o0 = fmaf(w111, f111.x, o0);  o1 = fmaf(w111, f111.y, o1);

    // half-warp writes one contiguous 128B line; streaming store keeps L2
    // capacity for the hash table.
    store_cs_f2(out + (uint32_t)point * NGP_LEVELS + (uint32_t)level, o0, o1);
}

extern "C" void kernel_launch(void* const* d_in, const int* in_sizes, int n_in,
                              void* d_out, int out_size)
{
    const float* x     = (const float*)d_in[0];
    const float* table = (const float*)d_in[1];
    float2* out        = (float2*)d_out;

    const int n_points = in_sizes[0] / 3;

    // Resolutions computed in double on host each call (deterministic);
    // matches the f32 reference floor on every level boundary.
    ResArr res;
    const double s = 1.4472692012786865;
    for (int l = 0; l < NGP_LEVELS; ++l) {
        res.r[l] = floorf((float)(16.0 * pow(s, (double)l)));
    }

    const int total   = n_points * NGP_LEVELS;
    const int threads = 256;
    const int blocks  = (total + threads - 1) / threads;

    ngp_hashgrid_kernel<<<blocks, threads>>>(x, table, out, res, n_points);
}

// round 6
// speedup vs baseline: 1.0882x; 1.0882x over previous
#include <cuda_runtime.h>
#include <cuda_bf16.h>
#include <math.h>
#include <stdint.h>

// Instant-NGP HashGrid encoding, two-kernel split:
//   Kernel A: levels 2..15 via direct hashed gathers (L1tex wavefront bound).
//             Lanes for levels 0,1 exit immediately -> 28 active lanes/warp
//             -> 14/16 of the gather wavefront work.
//   Kernel B: levels 0,1 via dense de-hashed SMEM caches (17^3 + 24^3 float2
//             = 149.9KB/block), gathers become LDS, one st.v4 per point.
//
//   x:     [N, 3]  float32 in [0,1)
//   table: [16, 2^19, 2] float32
//   out:   [N, 32] float32

#define NGP_LEVELS 16
#define NGP_LOG2T  19
#define NGP_T      (1u << NGP_LOG2T)
#define NGP_TMASK  (NGP_T - 1u)

#define PRIME_Y 2654435761u
#define PRIME_Z 805459861u

#define L0_R 17   // level-0 corner coords 0..16
#define L1_R 24   // level-1 corner coords 0..23
#define L0_N (L0_R * L0_R * L0_R)   // 4913
#define L1_N (L1_R * L1_R * L1_R)   // 13824
#define B_SMEM_BYTES ((L0_N + L1_N) * 8)   // 149896

struct ResArr { float r[NGP_LEVELS]; };

__device__ __forceinline__ void store_cs_f2(float2* p, float a, float b) {
    asm volatile("st.global.cs.v2.f32 [%0], {%1, %2};"
                 :: "l"(p), "f"(a), "f"(b) : "memory");
}
__device__ __forceinline__ void store_cs_f4(float4* p, float a, float b, float c, float d) {
    asm volatile("st.global.cs.v4.f32 [%0], {%1, %2, %3, %4};"
                 :: "l"(p), "f"(a), "f"(b), "f"(c), "f"(d) : "memory");
}

// ───────────────────────── Kernel A: hashed levels 2..15 ─────────────────────
__global__ __launch_bounds__(256)
void ngp_hash_kernel(const float* __restrict__ x,
                     const float* __restrict__ table,
                     float2* __restrict__ out,
                     ResArr res,
                     int n_points)
{
    int tid = blockIdx.x * blockDim.x + threadIdx.x;
    int point = tid >> 4;
    int level = tid & 15;
    if (point >= n_points) return;
    if (level < 2) return;   // levels 0,1 handled by kernel B

    const float cx = __ldg(x + point * 3 + 0);
    const float cy = __ldg(x + point * 3 + 1);
    const float cz = __ldg(x + point * 3 + 2);

    const float r = res.r[level];

    const float px = cx * r;
    const float py = cy * r;
    const float pz = cz * r;

    const float p0x = floorf(px);
    const float p0y = floorf(py);
    const float p0z = floorf(pz);

    const float fx = px - p0x;
    const float fy = py - p0y;
    const float fz = pz - p0z;

    const uint32_t ix = (uint32_t)p0x;
    const uint32_t iy = (uint32_t)p0y;
    const uint32_t iz = (uint32_t)p0z;

    const uint32_t hx0 = ix;
    const uint32_t hx1 = ix + 1u;
    const uint32_t hy0 = iy * PRIME_Y;
    const uint32_t hy1 = (iy + 1u) * PRIME_Y;
    const uint32_t hz0 = iz * PRIME_Z;
    const uint32_t hz1 = (iz + 1u) * PRIME_Z;

    const uint32_t m00 = hy0 ^ hz0;
    const uint32_t m10 = hy1 ^ hz0;
    const uint32_t m01 = hy0 ^ hz1;
    const uint32_t m11 = hy1 ^ hz1;

    const float2* __restrict__ tl =
        reinterpret_cast<const float2*>(table) + (uint32_t)level * NGP_T;

    const float2 f000 = __ldg(tl + ((hx0 ^ m00) & NGP_TMASK));
    const float2 f100 = __ldg(tl + ((hx1 ^ m00) & NGP_TMASK));
    const float2 f010 = __ldg(tl + ((hx0 ^ m10) & NGP_TMASK));
    const float2 f110 = __ldg(tl + ((hx1 ^ m10) & NGP_TMASK));
    const float2 f001 = __ldg(tl + ((hx0 ^ m01) & NGP_TMASK));
    const float2 f101 = __ldg(tl + ((hx1 ^ m01) & NGP_TMASK));
    const float2 f011 = __ldg(tl + ((hx0 ^ m11) & NGP_TMASK));
    const float2 f111 = __ldg(tl + ((hx1 ^ m11) & NGP_TMASK));

    const float gx = 1.0f - fx;
    const float gy = 1.0f - fy;
    const float gz = 1.0f - fz;

    const float wz0y0 = gy * gz;
    const float wz0y1 = fy * gz;
    const float wz1y0 = gy * fz;
    const float wz1y1 = fy * fz;

    const float w000 = gx * wz0y0;
    const float w100 = fx * wz0y0;
    const float w010 = gx * wz0y1;
    const float w110 = fx * wz0y1;
    const float w001 = gx * wz1y0;
    const float w101 = fx * wz1y0;
    const float w011 = gx * wz1y1;
    const float w111 = fx * wz1y1;

    float o0 = w000 * f000.x;
    float o1 = w000 * f000.y;
    o0 = fmaf(w100, f100.x, o0);  o1 = fmaf(w100, f100.y, o1);
    o0 = fmaf(w010, f010.x, o0);  o1 = fmaf(w010, f010.y, o1);
    o0 = fmaf(w110, f110.x, o0);  o1 = fmaf(w110, f110.y, o1);
    o0 = fmaf(w001, f001.x, o0);  o1 = fmaf(w001, f001.y, o1);
    o0 = fmaf(w101, f101.x, o0);  o1 = fmaf(w101, f101.y, o1);
    o0 = fmaf(w011, f011.x, o0);  o1 = fmaf(w011, f011.y, o1);
    o0 = fmaf(w111, f111.x, o0);  o1 = fmaf(w111, f111.y, o1);

    store_cs_f2(out + (uint32_t)point * NGP_LEVELS + (uint32_t)level, o0, o1);
}

// ─────────────────── Kernel B: levels 0,1 via dense SMEM cache ───────────────
__device__ __forceinline__ void interp_level(const float2* __restrict__ s,
                                             int R, float r,
                                             float cx, float cy, float cz,
                                             float& o0, float& o1)
{
    const float px = cx * r, py = cy * r, pz = cz * r;
    const float p0x = floorf(px), p0y = floorf(py), p0z = floorf(pz);
    const float fx = px - p0x, fy = py - p0y, fz = pz - p0z;

    const int ix = (int)p0x, iy = (int)p0y, iz = (int)p0z;
    const int R2 = R * R;
    const int base = ix * R2 + iy * R + iz;

    const float2 f000 = s[base];
    const float2 f100 = s[base + R2];
    const float2 f010 = s[base + R];
    const float2 f110 = s[base + R2 + R];
    const float2 f001 = s[base + 1];
    const float2 f101 = s[base + R2 + 1];
    const float2 f011 = s[base + R + 1];
    const float2 f111 = s[base + R2 + R + 1];

    const float gx = 1.0f - fx, gy = 1.0f - fy, gz = 1.0f - fz;
    const float wz0y0 = gy * gz, wz0y1 = fy * gz;
    const float wz1y0 = gy * fz, wz1y1 = fy * fz;

    const float w000 = gx * wz0y0, w100 = fx * wz0y0;
    const float w010 = gx * wz0y1, w110 = fx * wz0y1;
    const float w001 = gx * wz1y0, w101 = fx * wz1y0;
    const float w011 = gx * wz1y1, w111 = fx * wz1y1;

    o0 = w000 * f000.x;
    o1 = w000 * f000.y;
    o0 = fmaf(w100, f100.x, o0);  o1 = fmaf(w100, f100.y, o1);
    o0 = fmaf(w010, f010.x, o0);  o1 = fmaf(w010, f010.y, o1);
    o0 = fmaf(w110, f110.x, o0);  o1 = fmaf(w110, f110.y, o1);
    o0 = fmaf(w001, f001.x, o0);  o1 = fmaf(w001, f001.y, o1);
    o0 = fmaf(w101, f101.x, o0);  o1 = fmaf(w101, f101.y, o1);
    o0 = fmaf(w011, f011.x, o0);  o1 = fmaf(w011, f011.y, o1);
    o0 = fmaf(w111, f111.x, o0);  o1 = fmaf(w111, f111.y, o1);
}

__global__ __launch_bounds__(512)
void ngp_coarse_kernel(const float* __restrict__ x,
                       const float* __restrict__ table,
                       float4* __restrict__ out,  // out rows as float4[8]
                       int n_points)
{
    extern __shared__ float2 smem[];
    float2* s0 = smem;            // level-0 dense 17^3
    float2* s1 = smem + L0_N;     // level-1 dense 24^3

    const float2* __restrict__ t0 = reinterpret_cast<const float2*>(table);
    const float2* __restrict__ t1 = t0 + NGP_T;

    // Build de-hashed dense caches.
    for (int idx = threadIdx.x; idx < L0_N; idx += blockDim.x) {
        int ix = idx / (L0_R * L0_R);
        int rem = idx - ix * (L0_R * L0_R);
        int iy = rem / L0_R;
        int iz = rem - iy * L0_R;
        uint32_t h = ((uint32_t)ix ^ ((uint32_t)iy * PRIME_Y) ^ ((uint32_t)iz * PRIME_Z)) & NGP_TMASK;
        s0[idx] = __ldg(t0 + h);
    }
    for (int idx = threadIdx.x; idx < L1_N; idx += blockDim.x) {
        int ix = idx / (L1_R * L1_R);
        int rem = idx - ix * (L1_R * L1_R);
        int iy = rem / L1_R;
        int iz = rem - iy * L1_R;
        uint32_t h = ((uint32_t)ix ^ ((uint32_t)iy * PRIME_Y) ^ ((uint32_t)iz * PRIME_Z)) & NGP_TMASK;
        s1[idx] = __ldg(t1 + h);
    }
    __syncthreads();

    // Each block handles a contiguous chunk of points.
    const int chunk = (n_points + gridDim.x - 1) / gridDim.x;
    const int pbeg = blockIdx.x * chunk;
    const int pend = min(pbeg + chunk, n_points);

    for (int p = pbeg + threadIdx.x; p < pend; p += blockDim.x) {
        const float cx = __ldg(x + p * 3 + 0);
        const float cy = __ldg(x + p * 3 + 1);
        const float cz = __ldg(x + p * 3 + 2);

        float a0, a1, b0, b1;
        interp_level(s0, L0_R, 16.0f, cx, cy, cz, a0, a1);
        interp_level(s1, L1_R, 23.0f, cx, cy, cz, b0, b1);

        // out[p, 0..3] = {lvl0.f0, lvl0.f1, lvl1.f0, lvl1.f1}
        store_cs_f4(out + (uint32_t)p * 8, a0, a1, b0, b1);
    }
}

extern "C" void kernel_launch(void* const* d_in, const int* in_sizes, int n_in,
                              void* d_out, int out_size)
{
    const float* x     = (const float*)d_in[0];
    const float* table = (const float*)d_in[1];

    const int n_points = in_sizes[0] / 3;

    // Resolutions in double on host (matches f32 reference floor at every
    // level boundary, incl. res15 = 4095).
    ResArr res;
    const double s = 1.4472692012786865;
    for (int l = 0; l < NGP_LEVELS; ++l) {
        res.r[l] = floorf((float)(16.0 * pow(s, (double)l)));
    }

    // Opt-in to >48KB dynamic smem for kernel B. Unconditional (idempotent,
    // non-stream, capture-safe) so every kernel_launch call is identical —
    // no static guards per the harness rules.
    cudaFuncSetAttribute(ngp_coarse_kernel,
                         cudaFuncAttributeMaxDynamicSharedMemorySize,
                         B_SMEM_BYTES);

    // Kernel B: levels 0,1 (dense smem caches), one block per SM.
    ngp_coarse_kernel<<<148, 512, B_SMEM_BYTES>>>(x, table, (float4*)d_out, n_points);

    // Kernel A: levels 2..15 (hashed gathers).
    const int total   = n_points * NGP_LEVELS;
    const int threads = 256;
    const int blocks  = (total + threads - 1) / threads;
    ngp_hash_kernel<<<blocks, threads>>>(x, table, (float2*)d_out, res, n_points);
}

// round 7
// speedup vs baseline: 1.1011x; 1.0119x over previous
#include <cuda_runtime.h>
#include <cuda_bf16.h>
#include <math.h>
#include <stdint.h>

// Instant-NGP HashGrid encoding, three-kernel pipeline:
//   Prepass: de-hash levels 0,1 into a dense global scratch (150KB) ONCE.
//   Kernel B: levels 0,1 — smem caches filled by COALESCED copy from scratch
//             (not per-block hashed gathers), interp via LDS, st.v4 output.
//   Kernel A: levels 2..15 via direct hashed gathers (L1tex wavefront bound).
//
//   x:     [N, 3]  float32 in [0,1)
//   table: [16, 2^19, 2] float32
//   out:   [N, 32] float32

#define NGP_LEVELS 16
#define NGP_LOG2T  19
#define NGP_T      (1u << NGP_LOG2T)
#define NGP_TMASK  (NGP_T - 1u)

#define PRIME_Y 2654435761u
#define PRIME_Z 805459861u

#define L0_R 17   // level-0 corner coords 0..16
#define L1_R 24   // level-1 corner coords 0..23
#define L0_N (L0_R * L0_R * L0_R)   // 4913
#define L1_N (L1_R * L1_R * L1_R)   // 13824
#define DENSE_N (L0_N + L1_N)       // 18737
#define B_SMEM_BYTES (DENSE_N * 8)  // 149896

// Dense de-hashed copies of levels 0,1 (global scratch; no allocation).
__device__ float2 g_dense[DENSE_N];

struct ResArr { float r[NGP_LEVELS]; };

__device__ __forceinline__ void store_cs_f2(float2* p, float a, float b) {
    asm volatile("st.global.cs.v2.f32 [%0], {%1, %2};"
                 :: "l"(p), "f"(a), "f"(b) : "memory");
}
__device__ __forceinline__ void store_cs_f4(float4* p, float a, float b, float c, float d) {
    asm volatile("st.global.cs.v4.f32 [%0], {%1, %2, %3, %4};"
                 :: "l"(p), "f"(a), "f"(b), "f"(c), "f"(d) : "memory");
}

// ───────────────── Prepass: de-hash levels 0,1 into g_dense ─────────────────
__global__ __launch_bounds__(256)
void ngp_dehash_kernel(const float* __restrict__ table)
{
    int idx = blockIdx.x * blockDim.x + threadIdx.x;
    if (idx >= DENSE_N) return;

    const float2* __restrict__ t0 = reinterpret_cast<const float2*>(table);

    int lvl, R, lidx;
    const float2* tl;
    if (idx < L0_N) { lvl = 0; R = L0_R; lidx = idx;        tl = t0; }
    else            { lvl = 1; R = L1_R; lidx = idx - L0_N; tl = t0 + NGP_T; }
    (void)lvl;

    int ix = lidx / (R * R);
    int rem = lidx - ix * (R * R);
    int iy = rem / R;
    int iz = rem - iy * R;

    uint32_t h = ((uint32_t)ix ^ ((uint32_t)iy * PRIME_Y) ^ ((uint32_t)iz * PRIME_Z)) & NGP_TMASK;
    g_dense[idx] = __ldg(tl + h);
}

// ───────────────────────── Kernel A: hashed levels 2..15 ─────────────────────
__global__ __launch_bounds__(256)
void ngp_hash_kernel(const float* __restrict__ x,
                     const float* __restrict__ table,
                     float2* __restrict__ out,
                     ResArr res,
                     int n_points)
{
    int tid = blockIdx.x * blockDim.x + threadIdx.x;
    int point = tid >> 4;
    int level = tid & 15;
    if (point >= n_points) return;
    if (level < 2) return;   // levels 0,1 handled by kernel B

    const float cx = __ldg(x + point * 3 + 0);
    const float cy = __ldg(x + point * 3 + 1);
    const float cz = __ldg(x + point * 3 + 2);

    const float r = res.r[level];

    const float px = cx * r;
    const float py = cy * r;
    const float pz = cz * r;

    const float p0x = floorf(px);
    const float p0y = floorf(py);
    const float p0z = floorf(pz);

    const float fx = px - p0x;
    const float fy = py - p0y;
    const float fz = pz - p0z;

    const uint32_t ix = (uint32_t)p0x;
    const uint32_t iy = (uint32_t)p0y;
    const uint32_t iz = (uint32_t)p0z;

    const uint32_t hx0 = ix;
    const uint32_t hx1 = ix + 1u;
    const uint32_t hy0 = iy * PRIME_Y;
    const uint32_t hy1 = (iy + 1u) * PRIME_Y;
    const uint32_t hz0 = iz * PRIME_Z;
    const uint32_t hz1 = (iz + 1u) * PRIME_Z;

    const uint32_t m00 = hy0 ^ hz0;
    const uint32_t m10 = hy1 ^ hz0;
    const uint32_t m01 = hy0 ^ hz1;
    const uint32_t m11 = hy1 ^ hz1;

    const float2* __restrict__ tl =
        reinterpret_cast<const float2*>(table) + (uint32_t)level * NGP_T;

    const float2 f000 = __ldg(tl + ((hx0 ^ m00) & NGP_TMASK));
    const float2 f100 = __ldg(tl + ((hx1 ^ m00) & NGP_TMASK));
    const float2 f010 = __ldg(tl + ((hx0 ^ m10) & NGP_TMASK));
    const float2 f110 = __ldg(tl + ((hx1 ^ m10) & NGP_TMASK));
    const float2 f001 = __ldg(tl + ((hx0 ^ m01) & NGP_TMASK));
    const float2 f101 = __ldg(tl + ((hx1 ^ m01) & NGP_TMASK));
    const float2 f011 = __ldg(tl + ((hx0 ^ m11) & NGP_TMASK));
    const float2 f111 = __ldg(tl + ((hx1 ^ m11) & NGP_TMASK));

    const float gx = 1.0f - fx;
    const float gy = 1.0f - fy;
    const float gz = 1.0f - fz;

    const float wz0y0 = gy * gz;
    const float wz0y1 = fy * gz;
    const float wz1y0 = gy * fz;
    const float wz1y1 = fy * fz;

    const float w000 = gx * wz0y0;
    const float w100 = fx * wz0y0;
    const float w010 = gx * wz0y1;
    const float w110 = fx * wz0y1;
    const float w001 = gx * wz1y0;
    const float w101 = fx * wz1y0;
    const float w011 = gx * wz1y1;
    const float w111 = fx * wz1y1;

    float o0 = w000 * f000.x;
    float o1 = w000 * f000.y;
    o0 = fmaf(w100, f100.x, o0);  o1 = fmaf(w100, f100.y, o1);
    o0 = fmaf(w010, f010.x, o0);  o1 = fmaf(w010, f010.y, o1);
    o0 = fmaf(w110, f110.x, o0);  o1 = fmaf(w110, f110.y, o1);
    o0 = fmaf(w001, f001.x, o0);  o1 = fmaf(w001, f001.y, o1);
    o0 = fmaf(w101, f101.x, o0);  o1 = fmaf(w101, f101.y, o1);
    o0 = fmaf(w011, f011.x, o0);  o1 = fmaf(w011, f011.y, o1);
    o0 = fmaf(w111, f111.x, o0);  o1 = fmaf(w111, f111.y, o1);

    store_cs_f2(out + (uint32_t)point * NGP_LEVELS + (uint32_t)level, o0, o1);
}

// ─────────────────── Kernel B: levels 0,1 via dense SMEM cache ───────────────
__device__ __forceinline__ void interp_level(const float2* __restrict__ s,
                                             int R, float r,
                                             float cx, float cy, float cz,
                                             float& o0, float& o1)
{
    const float px = cx * r, py = cy * r, pz = cz * r;
    const float p0x = floorf(px), p0y = floorf(py), p0z = floorf(pz);
    const float fx = px - p0x, fy = py - p0y, fz = pz - p0z;

    const int ix = (int)p0x, iy = (int)p0y, iz = (int)p0z;
    const int R2 = R * R;
    const int base = ix * R2 + iy * R + iz;

    const float2 f000 = s[base];
    const float2 f100 = s[base + R2];
    const float2 f010 = s[base + R];
    const float2 f110 = s[base + R2 + R];
    const float2 f001 = s[base + 1];
    const float2 f101 = s[base + R2 + 1];
    const float2 f011 = s[base + R + 1];
    const float2 f111 = s[base + R2 + R + 1];

    const float gx = 1.0f - fx, gy = 1.0f - fy, gz = 1.0f - fz;
    const float wz0y0 = gy * gz, wz0y1 = fy * gz;
    const float wz1y0 = gy * fz, wz1y1 = fy * fz;

    const float w000 = gx * wz0y0, w100 = fx * wz0y0;
    const float w010 = gx * wz0y1, w110 = fx * wz0y1;
    const float w001 = gx * wz1y0, w101 = fx * wz1y0;
    const float w011 = gx * wz1y1, w111 = fx * wz1y1;

    o0 = w000 * f000.x;
    o1 = w000 * f000.y;
    o0 = fmaf(w100, f100.x, o0);  o1 = fmaf(w100, f100.y, o1);
    o0 = fmaf(w010, f010.x, o0);  o1 = fmaf(w010, f010.y, o1);
    o0 = fmaf(w110, f110.x, o0);  o1 = fmaf(w110, f110.y, o1);
    o0 = fmaf(w001, f001.x, o0);  o1 = fmaf(w001, f001.y, o1);
    o0 = fmaf(w101, f101.x, o0);  o1 = fmaf(w101, f101.y, o1);
    o0 = fmaf(w011, f011.x, o0);  o1 = fmaf(w011, f011.y, o1);
    o0 = fmaf(w111, f111.x, o0);  o1 = fmaf(w111, f111.y, o1);
}

__global__ __launch_bounds__(1024, 1)
void ngp_coarse_kernel(const float* __restrict__ x,
                       float4* __restrict__ out,  // out rows as float4[8]
                       int n_points)
{
    extern __shared__ float2 smem[];
    float2* s0 = smem;            // level-0 dense 17^3
    float2* s1 = smem + L0_N;     // level-1 dense 24^3

    // Coalesced fill from the pre-de-hashed dense scratch (NOT hashed gathers).
    for (int idx = threadIdx.x; idx < DENSE_N; idx += blockDim.x) {
        smem[idx] = g_dense[idx];
    }
    __syncthreads();

    // Each block handles a contiguous chunk of points.
    const int chunk = (n_points + gridDim.x - 1) / gridDim.x;
    const int pbeg = blockIdx.x * chunk;
    const int pend = min(pbeg + chunk, n_points);

    for (int p = pbeg + threadIdx.x; p < pend; p += blockDim.x) {
        const float cx = __ldg(x + p * 3 + 0);
        const float cy = __ldg(x + p * 3 + 1);
        const float cz = __ldg(x + p * 3 + 2);

        float a0, a1, b0, b1;
        interp_level(s0, L0_R, 16.0f, cx, cy, cz, a0, a1);
        interp_level(s1, L1_R, 23.0f, cx, cy, cz, b0, b1);

        // out[p, 0..3] = {lvl0.f0, lvl0.f1, lvl1.f0, lvl1.f1}
        store_cs_f4(out + (uint32_t)p * 8, a0, a1, b0, b1);
    }
}

extern "C" void kernel_launch(void* const* d_in, const int* in_sizes, int n_in,
                              void* d_out, int out_size)
{
    const float* x     = (const float*)d_in[0];
    const float* table = (const float*)d_in[1];

    const int n_points = in_sizes[0] / 3;

    // Resolutions in double on host (matches f32 reference floor at every
    // level boundary, incl. res15 = 4095).
    ResArr res;
    const double s = 1.4472692012786865;
    for (int l = 0; l < NGP_LEVELS; ++l) {
        res.r[l] = floorf((float)(16.0 * pow(s, (double)l)));
    }

    // Opt-in to >48KB dynamic smem for kernel B. Unconditional (idempotent,
    // non-stream, capture-safe); every kernel_launch call does identical work.
    cudaFuncSetAttribute(ngp_coarse_kernel,
                         cudaFuncAttributeMaxDynamicSharedMemorySize,
                         B_SMEM_BYTES);

    // 1) De-hash levels 0,1 once into dense scratch (~19K gathers chip-wide).
    ngp_dehash_kernel<<<(DENSE_N + 255) / 256, 256>>>(table);

    // 2) Kernel B: levels 0,1 from smem (coalesced cache fill), 1 block/SM.
    ngp_coarse_kernel<<<148, 1024, B_SMEM_BYTES>>>(x, (float4*)d_out, n_points);

    // 3) Kernel A: levels 2..15 (hashed gathers).
    const int total   = n_points * NGP_LEVELS;
    const int threads = 256;
    const int blocks  = (total + threads - 1) / threads;
    ngp_hash_kernel<<<blocks, threads>>>(x, table, (float2*)d_out, res, n_points);
}